// round 8
// baseline (speedup 1.0000x reference)
#include <cuda_runtime.h>
#include <cuda_bf16.h>
#include <cstdint>
#include <math.h>

#define NV 10000
#define NF 80000
#define NE 160000
#define NTILES 2500            // 64-edge tiles
#define EDGE_GRID 148

// ---------------- edge-tile geometry: row stride 272 B (17*16, conflict-free)
#define ER 272
#define EA_LO 17408             // 64 rows * 272
#define EW_LO128 34816          // lo-plane offset inside a 128-row W block
#define EW_LO64  17408          // lo-plane offset inside a 64-row W block

// ---------------- GRU-tile geometry (row stride 272)
#define GR 272
#define GA_LO 34816             // 128 rows * 272
#define GW_LO 69632             // 256 rows * 272

// ---------------- persistent scratch ----------------
__device__ float g_var_h[NV * 64];
__device__ float g_fac_h[NF * 64];
__device__ float g_nm_var[NV * 64];
__device__ float g_nm_fac[NF * 64];
// per direction: W1 hi+lo 69632 | W2 hi+lo 69632 | W3 hi+lo 34816 = 174080
__device__ __align__(256) unsigned char g_wpack_f2v[174080];
__device__ __align__(256) unsigned char g_wpack_v2f[174080];
__device__ __align__(256) unsigned char g_wgru_gf[139264];   // 256x136 bf16 hi+lo
__device__ __align__(256) unsigned char g_wgru_gv[139264];

// ---------------- PTX helpers (sm_90 baseline; NO tcgen05) ----------------
__device__ __forceinline__ uint32_t smem_u32(const void* p) {
    uint32_t a;
    asm("{ .reg .u64 t; cvta.to.shared.u64 t, %1; cvt.u32.u64 %0, t; }" : "=r"(a) : "l"(p));
    return a;
}
#define MBARRIER_INIT(mbar, cnt) \
    asm volatile("mbarrier.init.shared.b64 [%0], %1;" :: "r"(mbar), "r"(cnt) : "memory")
#define MBARRIER_EXPECT_TX(mbar, bytes) \
    asm volatile("mbarrier.arrive.expect_tx.shared.b64 _, [%0], %1;" :: "r"(mbar), "r"(bytes) : "memory")
#define MBARRIER_WAIT_PARITY(mbar, ph) do { \
    asm volatile("{\n\t.reg .pred P1;\n\t" \
        "W_%=:\n\tmbarrier.try_wait.parity.acquire.cta.shared::cta.b64 P1, [%0], %1, 0x989680;\n\t" \
        "@P1 bra.uni D_%=;\n\tbra.uni W_%=;\n\tD_%=:\n\t}" \
        :: "r"(mbar), "r"(ph) : "memory"); \
} while (0)

__device__ __forceinline__ void bulk_copy_g2s(uint32_t dst, const void* src,
                                              uint32_t bytes, uint32_t mbar) {
    asm volatile(
        "cp.async.bulk.shared::cluster.global.mbarrier::complete_tx::bytes [%0], [%1], %2, [%3];"
        :: "r"(dst), "l"(src), "r"(bytes), "r"(mbar) : "memory");
}
__device__ __forceinline__ void ldsm4(uint32_t addr, uint32_t* r) {
    asm volatile("ldmatrix.sync.aligned.m8n8.x4.shared.b16 {%0,%1,%2,%3}, [%4];"
        : "=r"(r[0]), "=r"(r[1]), "=r"(r[2]), "=r"(r[3]) : "r"(addr));
}
__device__ __forceinline__ void mma16816(float* d, const uint32_t* a, const uint32_t* b) {
    asm volatile("mma.sync.aligned.m16n8k16.row.col.f32.bf16.bf16.f32 "
        "{%0,%1,%2,%3}, {%4,%5,%6,%7}, {%8,%9}, {%0,%1,%2,%3};"
        : "+f"(d[0]), "+f"(d[1]), "+f"(d[2]), "+f"(d[3])
        : "r"(a[0]), "r"(a[1]), "r"(a[2]), "r"(a[3]), "r"(b[0]), "r"(b[1]));
}
__device__ __forceinline__ void mma16808(float* d, const uint32_t* a, uint32_t b) {
    asm volatile("mma.sync.aligned.m16n8k8.row.col.f32.bf16.bf16.f32 "
        "{%0,%1,%2,%3}, {%4,%5}, {%6}, {%0,%1,%2,%3};"
        : "+f"(d[0]), "+f"(d[1]), "+f"(d[2]), "+f"(d[3])
        : "r"(a[0]), "r"(a[1]), "r"(b));
}

// ---------------- zero ----------------
__global__ void zero_kernel(float* __restrict__ p, int n) {
    int i = blockIdx.x * blockDim.x + threadIdx.x;
    for (; i < n; i += gridDim.x * blockDim.x) p[i] = 0.0f;
}

// ---------------- edge weight pre-pack: rows of 136 elems (272 B) ----------
__global__ void pack_weights_kernel(unsigned char* __restrict__ dst,
                                    const float* __restrict__ W,
                                    int nrows, int kin) {
    const int total = nrows * 136;
    const int plane = nrows * ER;
    for (int i = blockIdx.x * blockDim.x + threadIdx.x; i < total;
         i += gridDim.x * blockDim.x) {
        int n = i / 136, k = i - n * 136;
        float v = (k < kin) ? W[n * kin + k] : 0.0f;
        __nv_bfloat16 hi = __float2bfloat16(v);
        __nv_bfloat16 lo = __float2bfloat16(v - __bfloat162float(hi));
        uint32_t off = (uint32_t)n * ER + (uint32_t)k * 2;
        *(__nv_bfloat16*)(dst + off) = hi;
        *(__nv_bfloat16*)(dst + plane + off) = lo;
    }
}

// ---------------- GRU weight pre-pack: W' = [wr|hr; wz|hz; wn|0; 0|hn] ------
__global__ void pack_gru_kernel(unsigned char* __restrict__ dst,
                                const float* __restrict__ wih,
                                const float* __restrict__ whh) {
    const int total = 256 * 136;
    for (int i = blockIdx.x * blockDim.x + threadIdx.x; i < total;
         i += gridDim.x * blockDim.x) {
        int r = i / 136, k = i - r * 136;
        float v = 0.0f;
        if (k < 128) {
            if (r < 128)       v = (k < 64) ? wih[r * 64 + k] : whh[r * 64 + (k - 64)];
            else if (r < 192)  { if (k < 64)  v = wih[r * 64 + k]; }
            else               { if (k >= 64) v = whh[(r - 64) * 64 + (k - 64)]; }
        }
        __nv_bfloat16 hi = __float2bfloat16(v);
        __nv_bfloat16 lo = __float2bfloat16(v - __bfloat162float(hi));
        uint32_t off = (uint32_t)r * GR + (uint32_t)k * 2;
        *(__nv_bfloat16*)(dst + off) = hi;
        *(__nv_bfloat16*)(dst + GW_LO + off) = lo;
    }
}

// ---------------- generic HMMA tile: [M x K] x [N x K]^T, warp tile 32m x 16*NPAIR
template<int KCH, int NPAIR>
__device__ __forceinline__ void layer_mma_s(
    uint32_t aA, uint32_t aW, uint32_t rstr, uint32_t aLo, uint32_t wLo,
    int lane, int mbase, int nbase, float* acc)
{
    const uint32_t aRow = aA + (uint32_t)(mbase + (lane & 15)) * rstr + ((lane >> 4) << 4);
    const uint32_t bRow = aW + (uint32_t)(nbase + (lane & 7) + ((lane >> 4) << 3)) * rstr
                        + (((lane >> 3) & 1) << 4);
    #pragma unroll
    for (int kc = 0; kc < KCH; kc++) {
        uint32_t ah[8], al[8];
        ldsm4(aRow + kc * 32, ah);
        ldsm4(aRow + 16 * rstr + kc * 32, ah + 4);
        ldsm4(aRow + aLo + kc * 32, al);
        ldsm4(aRow + aLo + 16 * rstr + kc * 32, al + 4);
        #pragma unroll
        for (int np = 0; np < NPAIR; np++) {
            uint32_t bh[4], bl[4];
            ldsm4(bRow + np * 16 * rstr + kc * 32, bh);
            ldsm4(bRow + wLo + np * 16 * rstr + kc * 32, bl);
            #pragma unroll
            for (int m = 0; m < 2; m++) {
                #pragma unroll
                for (int h = 0; h < 2; h++) {
                    float* d = acc + ((m * NPAIR + np) * 2 + h) * 4;
                    mma16816(d, ah + m * 4, bh + h * 2);
                    mma16816(d, ah + m * 4, bl + h * 2);
                    mma16816(d, al + m * 4, bh + h * 2);
                }
            }
        }
    }
}

// k8 tail for layer 1 (cols 128..135, byte offset 256), warp tile 32m x 32n
__device__ __forceinline__ void layer1_tail(
    uint32_t aA, uint32_t aW, int lane, int mbase, int nbase, float* acc)
{
    const uint32_t aAddr = aA + (uint32_t)(mbase + lane) * ER + 256;
    const uint32_t bAddr = aW + (uint32_t)(nbase + lane) * ER + 256;
    uint32_t ah[4], al[4], bh[4], bl[4];
    ldsm4(aAddr, ah);
    ldsm4(aAddr + EA_LO, al);
    ldsm4(bAddr, bh);
    ldsm4(bAddr + EW_LO128, bl);
    #pragma unroll
    for (int m = 0; m < 2; m++)
        #pragma unroll
        for (int n4 = 0; n4 < 4; n4++) {
            float* d = acc + ((m * 2 + (n4 >> 1)) * 2 + (n4 & 1)) * 4;
            mma16808(d, ah + 2 * m, bh[n4]);
            mma16808(d, ah + 2 * m, bl[n4]);
            mma16808(d, al + 2 * m, bh[n4]);
        }
}

// epilogue edge layers 1/2: +bias, relu, hi/lo split, write back into A tile
__device__ __forceinline__ void epi12(unsigned char* Ab, const float* bias,
                                      int lane, int mbase, int nbase, const float* acc)
{
    #pragma unroll
    for (int m = 0; m < 2; m++)
        #pragma unroll
        for (int np = 0; np < 2; np++)
            #pragma unroll
            for (int h = 0; h < 2; h++) {
                const float* d = acc + ((m * 2 + np) * 2 + h) * 4;
                int c = nbase + np * 16 + h * 8 + 2 * (lane & 3);
                int r = mbase + m * 16 + (lane >> 2);
                float b0 = bias[c], b1 = bias[c + 1];
                float v0 = fmaxf(d[0] + b0, 0.f), v1 = fmaxf(d[1] + b1, 0.f);
                float v2 = fmaxf(d[2] + b0, 0.f), v3 = fmaxf(d[3] + b1, 0.f);
                __nv_bfloat162 hA = __floats2bfloat162_rn(v0, v1);
                __nv_bfloat162 lA = __floats2bfloat162_rn(v0 - __low2float(hA),
                                                          v1 - __high2float(hA));
                __nv_bfloat162 hB = __floats2bfloat162_rn(v2, v3);
                __nv_bfloat162 lB = __floats2bfloat162_rn(v2 - __low2float(hB),
                                                          v3 - __high2float(hB));
                uint32_t o0 = (uint32_t)r * ER + (uint32_t)c * 2;
                uint32_t o1 = o0 + 8u * ER;
                *(uint32_t*)(Ab + o0)         = *(uint32_t*)&hA;
                *(uint32_t*)(Ab + EA_LO + o0) = *(uint32_t*)&lA;
                *(uint32_t*)(Ab + o1)         = *(uint32_t*)&hB;
                *(uint32_t*)(Ab + EA_LO + o1) = *(uint32_t*)&lB;
            }
}

// ---------------- persistent edge MLP: weights resident, grid-strided tiles --
// smem: A hi+lo [34816] | W1 hi+lo [69632] | W2 hi+lo [69632] | W3 hi+lo [34816]
//       | rs[256] cs[256] bias[1280] mbar[16]
#define SM_W1   34816
#define SM_W2   104448
#define SM_W3   174080
#define SM_RS   208896
#define SM_CS   209152
#define SM_BIAS 209408
#define SM_MBW  210688
#define EDGE_SMEM_BYTES 210720
__global__ __launch_bounds__(256, 1) void edge_mma_kernel(
    const float* __restrict__ Ah, const float* __restrict__ Bh,
    const int* __restrict__ rowi, const int* __restrict__ coli,
    const float* __restrict__ feat,
    const unsigned char* __restrict__ wsrc,
    const float* __restrict__ b1, const float* __restrict__ b2,
    const float* __restrict__ b3,
    float* __restrict__ nm)
{
    extern __shared__ __align__(256) unsigned char sm[];
    const uint32_t smb = smem_u32(sm);
    const int tid = threadIdx.x;

    int*   rs     = (int*)(sm + SM_RS);
    int*   cs     = (int*)(sm + SM_CS);
    float* bias_s = (float*)(sm + SM_BIAS);
    const uint32_t mbw = smb + SM_MBW;

    if (tid == 0) MBARRIER_INIT(mbw, 1u);
    __syncthreads();
    if (tid == 0) {   // ALL weights, one copy per block, resident for all tiles
        MBARRIER_EXPECT_TX(mbw, 174080u);
        bulk_copy_g2s(smb + SM_W1, wsrc, 174080u, mbw);
    }
    for (int i = tid; i < 320; i += 256)
        bias_s[i] = (i < 128) ? b1[i] : (i < 256 ? b2[i - 128] : b3[i - 256]);

    const int w = tid >> 5, lane = tid & 31;
    const int mbase = (w & 1) * 32;
    const int nb32  = (w >> 1) * 32;
    const int nb16  = (w >> 1) * 16;
    float acc[32];
    bool first = true;

    for (int t = blockIdx.x; t < NTILES; t += EDGE_GRID) {
        const int e0 = t * 64;
        __syncthreads();   // previous tile fully consumed (A, rs, cs)
        if (tid < 64)        rs[tid] = rowi[e0 + tid];
        else if (tid < 128)  cs[tid - 64] = coli[e0 + tid - 64];
        __syncthreads();

        // gather A1 = [Ah[row](64) | Bh[col](64) | feat[row](4) | feat[col](4)]
        for (int i = tid; i < 64 * 34; i += 256) {
            int e = i / 34, q = i - e * 34;
            float4 x;
            if (q < 16)       x = *(const float4*)(Ah + (size_t)rs[e] * 64 + q * 4);
            else if (q < 32)  x = *(const float4*)(Bh + (size_t)cs[e] * 64 + (q - 16) * 4);
            else if (q == 32) x = *(const float4*)(feat + (size_t)rs[e] * 4);
            else              x = *(const float4*)(feat + (size_t)cs[e] * 4);
            __nv_bfloat162 h01 = __floats2bfloat162_rn(x.x, x.y);
            __nv_bfloat162 h23 = __floats2bfloat162_rn(x.z, x.w);
            __nv_bfloat162 l01 = __floats2bfloat162_rn(x.x - __low2float(h01), x.y - __high2float(h01));
            __nv_bfloat162 l23 = __floats2bfloat162_rn(x.z - __low2float(h23), x.w - __high2float(h23));
            uint32_t off = (uint32_t)e * ER + (uint32_t)q * 8;
            *(uint2*)(sm + off)         = make_uint2(*(uint32_t*)&h01, *(uint32_t*)&h23);
            *(uint2*)(sm + EA_LO + off) = make_uint2(*(uint32_t*)&l01, *(uint32_t*)&l23);
        }
        if (first) { MBARRIER_WAIT_PARITY(mbw, 0); first = false; }
        __syncthreads();

        // ---- layer 1: K=136 (8 k16 + k8 tail), N=128 ----
        #pragma unroll
        for (int i = 0; i < 32; i++) acc[i] = 0.f;
        layer_mma_s<8, 2>(smb, smb + SM_W1, ER, EA_LO, EW_LO128, lane, mbase, nb32, acc);
        layer1_tail(smb, smb + SM_W1, lane, mbase, nb32, acc);
        __syncthreads();
        epi12(sm, bias_s, lane, mbase, nb32, acc);
        __syncthreads();

        // ---- layer 2: K=128, N=128 ----
        #pragma unroll
        for (int i = 0; i < 32; i++) acc[i] = 0.f;
        layer_mma_s<8, 2>(smb, smb + SM_W2, ER, EA_LO, EW_LO128, lane, mbase, nb32, acc);
        __syncthreads();
        epi12(sm, bias_s + 128, lane, mbase, nb32, acc);
        __syncthreads();

        // ---- layer 3: K=128, N=64, scatter-add ----
        #pragma unroll
        for (int i = 0; i < 16; i++) acc[i] = 0.f;
        layer_mma_s<8, 1>(smb, smb + SM_W3, ER, EA_LO, EW_LO64, lane, mbase, nb16, acc);

        #pragma unroll
        for (int m = 0; m < 2; m++)
            #pragma unroll
            for (int h = 0; h < 2; h++) {
                const float* d = acc + (m * 2 + h) * 4;
                int c = nb16 + h * 8 + 2 * (lane & 3);
                int r = mbase + m * 16 + (lane >> 2);
                float b0 = bias_s[256 + c], b1v = bias_s[256 + c + 1];
                float* p0 = nm + (size_t)cs[r] * 64 + c;
                float* p1 = nm + (size_t)cs[r + 8] * 64 + c;
                atomicAdd(p0,     d[0] + b0);
                atomicAdd(p0 + 1, d[1] + b1v);
                atomicAdd(p1,     d[2] + b0);
                atomicAdd(p1 + 1, d[3] + b1v);
            }
    }
}

// ---------------- HMMA GRU: [x|h](128x128) @ W'(256x128)^T ------------------
#define GSM_W    69632
#define GSM_BIAS 208896
#define GSM_MBW  209920
#define GRU_SMEM_BYTES 209952
__global__ __launch_bounds__(512, 1) void gru_mma_kernel(
    float* __restrict__ h, float* __restrict__ x,
    const unsigned char* __restrict__ wsrc,
    const float* __restrict__ bih, const float* __restrict__ bhh,
    int nrows)
{
    extern __shared__ __align__(256) unsigned char sm[];
    const uint32_t smb = smem_u32(sm);
    const int tid = threadIdx.x;
    const int r0 = blockIdx.x * 128;

    float* bias_s = (float*)(sm + GSM_BIAS);
    float* gs     = (float*)(sm + GSM_W);
    const uint32_t mbw = smb + GSM_MBW;

    if (tid == 0) MBARRIER_INIT(mbw, 1u);
    __syncthreads();
    if (tid == 0) {
        MBARRIER_EXPECT_TX(mbw, 139264u);
        bulk_copy_g2s(smb + GSM_W, wsrc, 139264u, mbw);
    }
    for (int i = tid; i < 256; i += 512) {
        float v;
        if (i < 128)      v = bih[i] + bhh[i];
        else if (i < 192) v = bih[i];
        else              v = bhh[i - 64];
        bias_s[i] = v;
    }

    for (int i = tid; i < 128 * 32; i += 512) {
        int e = i >> 5, q = i & 31;
        int rr = r0 + e;
        int rc = rr < nrows ? rr : nrows - 1;
        float4 xv;
        if (q < 16) {
            xv = *(const float4*)(x + (size_t)rc * 64 + q * 4);
            if (rr < nrows) *(float4*)(x + (size_t)rc * 64 + q * 4) = make_float4(0.f, 0.f, 0.f, 0.f);
        } else {
            xv = *(const float4*)(h + (size_t)rc * 64 + (q - 16) * 4);
        }
        __nv_bfloat162 h01 = __floats2bfloat162_rn(xv.x, xv.y);
        __nv_bfloat162 h23 = __floats2bfloat162_rn(xv.z, xv.w);
        __nv_bfloat162 l01 = __floats2bfloat162_rn(xv.x - __low2float(h01), xv.y - __high2float(h01));
        __nv_bfloat162 l23 = __floats2bfloat162_rn(xv.z - __low2float(h23), xv.w - __high2float(h23));
        uint32_t off = (uint32_t)e * GR + (uint32_t)q * 8;
        *(uint2*)(sm + off)         = make_uint2(*(uint32_t*)&h01, *(uint32_t*)&h23);
        *(uint2*)(sm + GA_LO + off) = make_uint2(*(uint32_t*)&l01, *(uint32_t*)&l23);
    }
    __syncthreads();

    const int w = tid >> 5, lane = tid & 31;
    const int mbase = (w & 3) * 32;
    const int nbase = (w >> 2) * 64;
    float acc[64];
    #pragma unroll
    for (int i = 0; i < 64; i++) acc[i] = 0.f;

    MBARRIER_WAIT_PARITY(mbw, 0);
    layer_mma_s<8, 4>(smb, smb + GSM_W, GR, GA_LO, GW_LO, lane, mbase, nbase, acc);
    __syncthreads();

    #pragma unroll
    for (int m = 0; m < 2; m++)
        #pragma unroll
        for (int np = 0; np < 4; np++)
            #pragma unroll
            for (int hh = 0; hh < 2; hh++) {
                const float* d = acc + ((m * 4 + np) * 2 + hh) * 4;
                int c = nbase + np * 16 + hh * 8 + 2 * (lane & 3);
                int r = mbase + m * 16 + (lane >> 2);
                gs[r * 256 + c]           = d[0];
                gs[r * 256 + c + 1]       = d[1];
                gs[(r + 8) * 256 + c]     = d[2];
                gs[(r + 8) * 256 + c + 1] = d[3];
            }
    __syncthreads();

    for (int i = tid; i < 128 * 64; i += 512) {
        int e = i >> 6, d = i & 63;
        int r = r0 + e;
        if (r >= nrows) continue;
        const float* g = gs + e * 256;
        float pr = g[d]       + bias_s[d];
        float pz = g[64 + d]  + bias_s[64 + d];
        float in = g[128 + d] + bias_s[128 + d];
        float hn = g[192 + d] + bias_s[192 + d];
        float rr = 1.f / (1.f + expf(-pr));
        float zz = 1.f / (1.f + expf(-pz));
        float nn = tanhf(in + rr * hn);
        float hv = h[(size_t)r * 64 + d];
        h[(size_t)r * 64 + d] = (1.f - zz) * nn + zz * hv;
    }
}

// ---------------- readout ----------------
__global__ __launch_bounds__(256) void readout_kernel(
    const float* __restrict__ h,
    const float* __restrict__ W1, const float* __restrict__ b1,
    const float* __restrict__ W2, const float* __restrict__ b2,
    const float* __restrict__ W3, const float* __restrict__ b3,
    float* __restrict__ out, int nrows)
{
    __shared__ float hs[32 * 68];
    __shared__ float l1s[32 * 132];
    __shared__ float l2s[32 * 132];
    __shared__ float lg[64];

    const int tid = threadIdx.x;
    const int r0  = blockIdx.x * 32;

    for (int i = tid; i < 32 * 64; i += 256) {
        int e = i >> 6, k = i & 63;
        int r = r0 + e;
        hs[e * 68 + k] = (r < nrows) ? h[(size_t)r * 64 + k] : 0.f;
    }
    __syncthreads();

    const int warp = tid >> 5, lane = tid & 31;
    #pragma unroll
    for (int jc = 0; jc < 4; jc++) {
        const int j0 = warp * 16 + jc * 4;
        float a[4] = {0.f, 0.f, 0.f, 0.f};
        #pragma unroll
        for (int k = 0; k < 64; k += 4) {
            float4 xv = *(const float4*)(hs + lane * 68 + k);
            #pragma unroll
            for (int jj = 0; jj < 4; jj++) {
                float4 wv = *(const float4*)(W1 + (size_t)(j0 + jj) * 64 + k);
                a[jj] += wv.x * xv.x + wv.y * xv.y + wv.z * xv.z + wv.w * xv.w;
            }
        }
        #pragma unroll
        for (int jj = 0; jj < 4; jj++)
            l1s[lane * 132 + j0 + jj] = fmaxf(a[jj] + b1[j0 + jj], 0.f);
    }
    __syncthreads();
    #pragma unroll
    for (int jc = 0; jc < 4; jc++) {
        const int j0 = warp * 16 + jc * 4;
        float a[4] = {0.f, 0.f, 0.f, 0.f};
        #pragma unroll 2
        for (int k = 0; k < 128; k += 4) {
            float4 xv = *(const float4*)(l1s + lane * 132 + k);
            #pragma unroll
            for (int jj = 0; jj < 4; jj++) {
                float4 wv = *(const float4*)(W2 + (size_t)(j0 + jj) * 128 + k);
                a[jj] += wv.x * xv.x + wv.y * xv.y + wv.z * xv.z + wv.w * xv.w;
            }
        }
        #pragma unroll
        for (int jj = 0; jj < 4; jj++)
            l2s[lane * 132 + j0 + jj] = fmaxf(a[jj] + b2[j0 + jj], 0.f);
    }
    __syncthreads();
    if (tid < 64) {
        int e = tid >> 1, j = tid & 1;
        float a = 0.f;
        #pragma unroll 4
        for (int k = 0; k < 128; k += 4) {
            float4 xv = *(const float4*)(l2s + e * 132 + k);
            float4 wv = *(const float4*)(W3 + (size_t)j * 128 + k);
            a += wv.x * xv.x + wv.y * xv.y + wv.z * xv.z + wv.w * xv.w;
        }
        lg[e * 2 + j] = a + b3[j];
    }
    __syncthreads();
    if (tid < 64) {
        int e = tid >> 1, j = tid & 1;
        int r = r0 + e;
        if (r < nrows) {
            float self  = lg[e * 2 + j];
            float other = lg[e * 2 + (j ^ 1)];
            out[(size_t)r * 2 + j] = 1.f / (1.f + expf(other - self));
        }
    }
}

extern "C" void kernel_launch(void* const* d_in, const int* in_sizes, int n_in,
                              void* d_out, int out_size)
{
    const int*   f2v_row  = (const int*)d_in[0];
    const int*   f2v_col  = (const int*)d_in[1];
    const int*   v2f_row  = (const int*)d_in[2];
    const int*   v2f_col  = (const int*)d_in[3];
    const float* f2v_feat = (const float*)d_in[4];
    const float* v2f_feat = (const float*)d_in[5];
    const float* f2v_w1 = (const float*)d_in[6];   const float* f2v_b1 = (const float*)d_in[7];
    const float* f2v_w2 = (const float*)d_in[8];   const float* f2v_b2 = (const float*)d_in[9];
    const float* f2v_w3 = (const float*)d_in[10];  const float* f2v_b3 = (const float*)d_in[11];
    const float* v2f_w1 = (const float*)d_in[12];  const float* v2f_b1 = (const float*)d_in[13];
    const float* v2f_w2 = (const float*)d_in[14];  const float* v2f_b2 = (const float*)d_in[15];
    const float* v2f_w3 = (const float*)d_in[16];  const float* v2f_b3 = (const float*)d_in[17];
    const float* gf_wih = (const float*)d_in[18];  const float* gf_whh = (const float*)d_in[19];
    const float* gf_bih = (const float*)d_in[20];  const float* gf_bhh = (const float*)d_in[21];
    const float* gv_wih = (const float*)d_in[22];  const float* gv_whh = (const float*)d_in[23];
    const float* gv_bih = (const float*)d_in[24];  const float* gv_bhh = (const float*)d_in[25];
    const float* ro_w1  = (const float*)d_in[26];  const float* ro_b1  = (const float*)d_in[27];
    const float* ro_w2  = (const float*)d_in[28];  const float* ro_b2  = (const float*)d_in[29];
    const float* ro_w3  = (const float*)d_in[30];  const float* ro_b3  = (const float*)d_in[31];
    float* out = (float*)d_out;

    float *var_h, *fac_h, *nm_var, *nm_fac;
    unsigned char *wp_f2v, *wp_v2f, *wg_gf, *wg_gv;
    cudaGetSymbolAddress((void**)&var_h,  g_var_h);
    cudaGetSymbolAddress((void**)&fac_h,  g_fac_h);
    cudaGetSymbolAddress((void**)&nm_var, g_nm_var);
    cudaGetSymbolAddress((void**)&nm_fac, g_nm_fac);
    cudaGetSymbolAddress((void**)&wp_f2v, g_wpack_f2v);
    cudaGetSymbolAddress((void**)&wp_v2f, g_wpack_v2f);
    cudaGetSymbolAddress((void**)&wg_gf,  g_wgru_gf);
    cudaGetSymbolAddress((void**)&wg_gv,  g_wgru_gv);

    cudaFuncSetAttribute(edge_mma_kernel, cudaFuncAttributeMaxDynamicSharedMemorySize, EDGE_SMEM_BYTES);
    cudaFuncSetAttribute(gru_mma_kernel,  cudaFuncAttributeMaxDynamicSharedMemorySize, GRU_SMEM_BYTES);

    pack_weights_kernel<<<32, 256>>>(wp_f2v,           f2v_w1, 128, 136);
    pack_weights_kernel<<<32, 256>>>(wp_f2v + 69632,   f2v_w2, 128, 128);
    pack_weights_kernel<<<32, 256>>>(wp_f2v + 139264,  f2v_w3,  64, 128);
    pack_weights_kernel<<<32, 256>>>(wp_v2f,           v2f_w1, 128, 136);
    pack_weights_kernel<<<32, 256>>>(wp_v2f + 69632,   v2f_w2, 128, 128);
    pack_weights_kernel<<<32, 256>>>(wp_v2f + 139264,  v2f_w3,  64, 128);
    pack_gru_kernel<<<32, 256>>>(wg_gf, gf_wih, gf_whh);
    pack_gru_kernel<<<32, 256>>>(wg_gv, gv_wih, gv_whh);

    zero_kernel<<<256, 256>>>(var_h, NV * 64);
    zero_kernel<<<512, 256>>>(fac_h, NF * 64);
    zero_kernel<<<256, 256>>>(nm_var, NV * 64);
    zero_kernel<<<512, 256>>>(nm_fac, NF * 64);

    for (int s = 0; s < 5; s++) {
        edge_mma_kernel<<<EDGE_GRID, 256, EDGE_SMEM_BYTES>>>(
            fac_h, var_h, f2v_row, f2v_col, f2v_feat, wp_f2v,
            f2v_b1, f2v_b2, f2v_b3, nm_var);
        gru_mma_kernel<<<(NV + 127) / 128, 512, GRU_SMEM_BYTES>>>(
            var_h, nm_var, wg_gf, gf_bih, gf_bhh, NV);

        edge_mma_kernel<<<EDGE_GRID, 256, EDGE_SMEM_BYTES>>>(
            var_h, fac_h, v2f_row, v2f_col, v2f_feat, wp_v2f,
            v2f_b1, v2f_b2, v2f_b3, nm_fac);
        gru_mma_kernel<<<NF / 128, 512, GRU_SMEM_BYTES>>>(
            fac_h, nm_fac, wg_gv, gv_bih, gv_bhh, NF);
    }

    readout_kernel<<<(NV + 31) / 32, 256>>>(
        var_h, ro_w1, ro_b1, ro_w2, ro_b2, ro_w3, ro_b3, out, NV);
}

// round 9
// speedup vs baseline: 1.3379x; 1.3379x over previous
#include <cuda_runtime.h>
#include <cuda_bf16.h>
#include <cstdint>
#include <math.h>

#define NV 10000
#define NF 80000
#define NE 160000

// ---------------- edge-tile geometry: row stride 272 B (17*16, conflict-free)
#define ER 272
#define EA_LO 17408             // 64 rows * 272
#define EW_LO128 34816          // lo-plane offset inside a 128-row W block
#define EW_LO64  17408          // lo-plane offset inside a 64-row W block

// ---------------- GRU-tile geometry (row stride 272)
#define GR 272
#define GA_LO 34816             // 128 rows * 272
#define GW_LO 69632             // 256 rows * 272

// ---------------- persistent scratch ----------------
__device__ float g_var_h[NV * 64];
__device__ float g_fac_h[NF * 64];
__device__ float g_nm_var[NV * 64];
__device__ float g_nm_fac[NF * 64];
// bf16 hi/lo planes of the states (maintained by GRU epilogue)
__device__ __nv_bfloat16 g_var_hhi[NV * 64];
__device__ __nv_bfloat16 g_var_hlo[NV * 64];
__device__ __nv_bfloat16 g_fac_hhi[NF * 64];
__device__ __nv_bfloat16 g_fac_hlo[NF * 64];
// feats pre-split (static)
__device__ __nv_bfloat16 g_f2v_fhi[NE * 4];
__device__ __nv_bfloat16 g_f2v_flo[NE * 4];
__device__ __nv_bfloat16 g_v2f_fhi[NE * 4];
__device__ __nv_bfloat16 g_v2f_flo[NE * 4];
// per direction: W1 hi+lo 69632 | W2 hi+lo 69632 | W3 hi+lo 34816 = 174080
__device__ __align__(256) unsigned char g_wpack_f2v[174080];
__device__ __align__(256) unsigned char g_wpack_v2f[174080];
__device__ __align__(256) unsigned char g_wgru_gf[139264];   // 256x136 bf16 hi+lo
__device__ __align__(256) unsigned char g_wgru_gv[139264];

// ---------------- PTX helpers (sm_90 baseline; NO tcgen05) ----------------
__device__ __forceinline__ uint32_t smem_u32(const void* p) {
    uint32_t a;
    asm("{ .reg .u64 t; cvta.to.shared.u64 t, %1; cvt.u32.u64 %0, t; }" : "=r"(a) : "l"(p));
    return a;
}
#define MBARRIER_INIT(mbar, cnt) \
    asm volatile("mbarrier.init.shared.b64 [%0], %1;" :: "r"(mbar), "r"(cnt) : "memory")
#define MBARRIER_EXPECT_TX(mbar, bytes) \
    asm volatile("mbarrier.arrive.expect_tx.shared.b64 _, [%0], %1;" :: "r"(mbar), "r"(bytes) : "memory")
#define MBARRIER_WAIT_PARITY(mbar, ph) do { \
    asm volatile("{\n\t.reg .pred P1;\n\t" \
        "W_%=:\n\tmbarrier.try_wait.parity.acquire.cta.shared::cta.b64 P1, [%0], %1, 0x989680;\n\t" \
        "@P1 bra.uni D_%=;\n\tbra.uni W_%=;\n\tD_%=:\n\t}" \
        :: "r"(mbar), "r"(ph) : "memory"); \
} while (0)

__device__ __forceinline__ void bulk_copy_g2s(uint32_t dst, const void* src,
                                              uint32_t bytes, uint32_t mbar) {
    asm volatile(
        "cp.async.bulk.shared::cluster.global.mbarrier::complete_tx::bytes [%0], [%1], %2, [%3];"
        :: "r"(dst), "l"(src), "r"(bytes), "r"(mbar) : "memory");
}
__device__ __forceinline__ void ldsm4(uint32_t addr, uint32_t* r) {
    asm volatile("ldmatrix.sync.aligned.m8n8.x4.shared.b16 {%0,%1,%2,%3}, [%4];"
        : "=r"(r[0]), "=r"(r[1]), "=r"(r[2]), "=r"(r[3]) : "r"(addr));
}
__device__ __forceinline__ void mma16816(float* d, const uint32_t* a, const uint32_t* b) {
    asm volatile("mma.sync.aligned.m16n8k16.row.col.f32.bf16.bf16.f32 "
        "{%0,%1,%2,%3}, {%4,%5,%6,%7}, {%8,%9}, {%0,%1,%2,%3};"
        : "+f"(d[0]), "+f"(d[1]), "+f"(d[2]), "+f"(d[3])
        : "r"(a[0]), "r"(a[1]), "r"(a[2]), "r"(a[3]), "r"(b[0]), "r"(b[1]));
}
__device__ __forceinline__ void mma16808(float* d, const uint32_t* a, uint32_t b) {
    asm volatile("mma.sync.aligned.m16n8k8.row.col.f32.bf16.bf16.f32 "
        "{%0,%1,%2,%3}, {%4,%5}, {%6}, {%0,%1,%2,%3};"
        : "+f"(d[0]), "+f"(d[1]), "+f"(d[2]), "+f"(d[3])
        : "r"(a[0]), "r"(a[1]), "r"(b));
}

// ---------------- zero ----------------
__global__ void zero_kernel(float* __restrict__ p, int n) {
    int i = blockIdx.x * blockDim.x + threadIdx.x;
    for (; i < n; i += gridDim.x * blockDim.x) p[i] = 0.0f;
}

// ---------------- generic fp32 -> hi/lo bf16 elementwise split --------------
__global__ void pack_split_kernel(__nv_bfloat16* __restrict__ hi_out,
                                  __nv_bfloat16* __restrict__ lo_out,
                                  const float* __restrict__ src, int n) {
    for (int i = blockIdx.x * blockDim.x + threadIdx.x; i < n;
         i += gridDim.x * blockDim.x) {
        float v = src[i];
        __nv_bfloat16 hi = __float2bfloat16(v);
        hi_out[i] = hi;
        lo_out[i] = __float2bfloat16(v - __bfloat162float(hi));
    }
}

// ---------------- edge weight pre-pack: rows of 136 elems (272 B) ----------
__global__ void pack_weights_kernel(unsigned char* __restrict__ dst,
                                    const float* __restrict__ W,
                                    int nrows, int kin) {
    const int total = nrows * 136;
    const int plane = nrows * ER;
    for (int i = blockIdx.x * blockDim.x + threadIdx.x; i < total;
         i += gridDim.x * blockDim.x) {
        int n = i / 136, k = i - n * 136;
        float v = (k < kin) ? W[n * kin + k] : 0.0f;
        __nv_bfloat16 hi = __float2bfloat16(v);
        __nv_bfloat16 lo = __float2bfloat16(v - __bfloat162float(hi));
        uint32_t off = (uint32_t)n * ER + (uint32_t)k * 2;
        *(__nv_bfloat16*)(dst + off) = hi;
        *(__nv_bfloat16*)(dst + plane + off) = lo;
    }
}

// ---------------- GRU weight pre-pack: W' = [wr|hr; wz|hz; wn|0; 0|hn] ------
__global__ void pack_gru_kernel(unsigned char* __restrict__ dst,
                                const float* __restrict__ wih,
                                const float* __restrict__ whh) {
    const int total = 256 * 136;
    for (int i = blockIdx.x * blockDim.x + threadIdx.x; i < total;
         i += gridDim.x * blockDim.x) {
        int r = i / 136, k = i - r * 136;
        float v = 0.0f;
        if (k < 128) {
            if (r < 128)       v = (k < 64) ? wih[r * 64 + k] : whh[r * 64 + (k - 64)];
            else if (r < 192)  { if (k < 64)  v = wih[r * 64 + k]; }
            else               { if (k >= 64) v = whh[(r - 64) * 64 + (k - 64)]; }
        }
        __nv_bfloat16 hi = __float2bfloat16(v);
        __nv_bfloat16 lo = __float2bfloat16(v - __bfloat162float(hi));
        uint32_t off = (uint32_t)r * GR + (uint32_t)k * 2;
        *(__nv_bfloat16*)(dst + off) = hi;
        *(__nv_bfloat16*)(dst + GW_LO + off) = lo;
    }
}

// ---------------- generic HMMA tile: [M x K] x [N x K]^T, warp tile 32m x 16*NPAIR
template<int KCH, int NPAIR>
__device__ __forceinline__ void layer_mma_s(
    uint32_t aA, uint32_t aW, uint32_t rstr, uint32_t aLo, uint32_t wLo,
    int lane, int mbase, int nbase, float* acc)
{
    const uint32_t aRow = aA + (uint32_t)(mbase + (lane & 15)) * rstr + ((lane >> 4) << 4);
    const uint32_t bRow = aW + (uint32_t)(nbase + (lane & 7) + ((lane >> 4) << 3)) * rstr
                        + (((lane >> 3) & 1) << 4);
    #pragma unroll
    for (int kc = 0; kc < KCH; kc++) {
        uint32_t ah[8], al[8];
        ldsm4(aRow + kc * 32, ah);
        ldsm4(aRow + 16 * rstr + kc * 32, ah + 4);
        ldsm4(aRow + aLo + kc * 32, al);
        ldsm4(aRow + aLo + 16 * rstr + kc * 32, al + 4);
        #pragma unroll
        for (int np = 0; np < NPAIR; np++) {
            uint32_t bh[4], bl[4];
            ldsm4(bRow + np * 16 * rstr + kc * 32, bh);
            ldsm4(bRow + wLo + np * 16 * rstr + kc * 32, bl);
            #pragma unroll
            for (int m = 0; m < 2; m++) {
                #pragma unroll
                for (int h = 0; h < 2; h++) {
                    float* d = acc + ((m * NPAIR + np) * 2 + h) * 4;
                    mma16816(d, ah + m * 4, bh + h * 2);
                    mma16816(d, ah + m * 4, bl + h * 2);
                    mma16816(d, al + m * 4, bh + h * 2);
                }
            }
        }
    }
}

// k8 tail for layer 1 (cols 128..135, byte offset 256), warp tile 32m x 32n
__device__ __forceinline__ void layer1_tail(
    uint32_t aA, uint32_t aW, int lane, int mbase, int nbase, float* acc)
{
    const uint32_t aAddr = aA + (uint32_t)(mbase + lane) * ER + 256;
    const uint32_t bAddr = aW + (uint32_t)(nbase + lane) * ER + 256;
    uint32_t ah[4], al[4], bh[4], bl[4];
    ldsm4(aAddr, ah);
    ldsm4(aAddr + EA_LO, al);
    ldsm4(bAddr, bh);
    ldsm4(bAddr + EW_LO128, bl);
    #pragma unroll
    for (int m = 0; m < 2; m++)
        #pragma unroll
        for (int n4 = 0; n4 < 4; n4++) {
            float* d = acc + ((m * 2 + (n4 >> 1)) * 2 + (n4 & 1)) * 4;
            mma16808(d, ah + 2 * m, bh[n4]);
            mma16808(d, ah + 2 * m, bl[n4]);
            mma16808(d, al + 2 * m, bh[n4]);
        }
}

// epilogue edge layers 1/2: +bias, relu, hi/lo split, write back into A tile
__device__ __forceinline__ void epi12(unsigned char* Ab, const float* bias,
                                      int lane, int mbase, int nbase, const float* acc)
{
    #pragma unroll
    for (int m = 0; m < 2; m++)
        #pragma unroll
        for (int np = 0; np < 2; np++)
            #pragma unroll
            for (int h = 0; h < 2; h++) {
                const float* d = acc + ((m * 2 + np) * 2 + h) * 4;
                int c = nbase + np * 16 + h * 8 + 2 * (lane & 3);
                int r = mbase + m * 16 + (lane >> 2);
                float b0 = bias[c], b1 = bias[c + 1];
                float v0 = fmaxf(d[0] + b0, 0.f), v1 = fmaxf(d[1] + b1, 0.f);
                float v2 = fmaxf(d[2] + b0, 0.f), v3 = fmaxf(d[3] + b1, 0.f);
                __nv_bfloat162 hA = __floats2bfloat162_rn(v0, v1);
                __nv_bfloat162 lA = __floats2bfloat162_rn(v0 - __low2float(hA),
                                                          v1 - __high2float(hA));
                __nv_bfloat162 hB = __floats2bfloat162_rn(v2, v3);
                __nv_bfloat162 lB = __floats2bfloat162_rn(v2 - __low2float(hB),
                                                          v3 - __high2float(hB));
                uint32_t o0 = (uint32_t)r * ER + (uint32_t)c * 2;
                uint32_t o1 = o0 + 8u * ER;
                *(uint32_t*)(Ab + o0)         = *(uint32_t*)&hA;
                *(uint32_t*)(Ab + EA_LO + o0) = *(uint32_t*)&lA;
                *(uint32_t*)(Ab + o1)         = *(uint32_t*)&hB;
                *(uint32_t*)(Ab + EA_LO + o1) = *(uint32_t*)&lB;
            }
}

// ---------------- fused edge MLP: 136->128->128->64, 64 edges/block, occ=2 --
// DIR=0 (fac->var): row = e>>1 (dup), col from idx, scatter = atomicAdd
// DIR=1 (var->fac): row from idx, col = e>>1 (dup), scatter = pair-sum store
#define SM_W    34816
#define SM_IDX  104448
#define SM_BIAS 104960
#define SM_MBW  106240
#define EDGE_SMEM_BYTES 106272
template<int DIR>
__global__ __launch_bounds__(256, 2) void edge_mma_kernel(
    const __nv_bfloat16* __restrict__ Ahi, const __nv_bfloat16* __restrict__ Alo,
    const __nv_bfloat16* __restrict__ Bhi, const __nv_bfloat16* __restrict__ Blo,
    const int* __restrict__ idxArr,
    const __nv_bfloat16* __restrict__ fhi, const __nv_bfloat16* __restrict__ flo,
    const unsigned char* __restrict__ wsrc,
    const float* __restrict__ b1, const float* __restrict__ b2,
    const float* __restrict__ b3,
    float* __restrict__ nm)
{
    extern __shared__ __align__(256) unsigned char sm[];
    const uint32_t smb = smem_u32(sm);
    const int tid = threadIdx.x;
    const int e0 = blockIdx.x * 64;
    const int p0 = e0 >> 1;   // base of the dup (pair) index

    int*   idx    = (int*)(sm + SM_IDX);
    float* bias_s = (float*)(sm + SM_BIAS);
    const uint32_t mbw = smb + SM_MBW;

    if (tid == 0) MBARRIER_INIT(mbw, 1u);
    __syncthreads();
    if (tid == 0) {
        MBARRIER_EXPECT_TX(mbw, 69632u);
        bulk_copy_g2s(smb + SM_W, wsrc, 69632u, mbw);
    }
    if (tid < 64) idx[tid] = idxArr[e0 + tid];
    for (int i = tid; i < 320; i += 256)
        bias_s[i] = (i < 128) ? b1[i] : (i < 256 ? b2[i - 128] : b3[i - 256]);
    __syncthreads();

    // ---- gather (pure bf16 copies, no conversion) ----
    // dup side: 32 unique rows x 8 segs, written to edge rows 2r and 2r+1
    {
        int r = tid >> 3, q = tid & 7;   // 256 threads = 32 x 8 exactly
        const __nv_bfloat16* srcH = (DIR == 0) ? Ahi : Bhi;
        const __nv_bfloat16* srcL = (DIR == 0) ? Alo : Blo;
        uint4 hv = *(const uint4*)(srcH + (size_t)(p0 + r) * 64 + q * 8);
        uint4 lv = *(const uint4*)(srcL + (size_t)(p0 + r) * 64 + q * 8);
        uint32_t cb = (DIR == 0) ? 0u : 128u;   // A cols 0-63 / B cols 64-127
        uint32_t o0 = (uint32_t)(2 * r)     * ER + cb + q * 16;
        uint32_t o1 = (uint32_t)(2 * r + 1) * ER + cb + q * 16;
        *(uint4*)(sm + o0)         = hv;  *(uint4*)(sm + o1)         = hv;
        *(uint4*)(sm + EA_LO + o0) = lv;  *(uint4*)(sm + EA_LO + o1) = lv;
    }
    // random side: 64 edges x 8 segs
    for (int i = tid; i < 512; i += 256) {
        int e = i >> 3, q = i & 7;
        int s = idx[e];
        const __nv_bfloat16* srcH = (DIR == 0) ? Bhi : Ahi;
        const __nv_bfloat16* srcL = (DIR == 0) ? Blo : Alo;
        uint4 hv = *(const uint4*)(srcH + (size_t)s * 64 + q * 8);
        uint4 lv = *(const uint4*)(srcL + (size_t)s * 64 + q * 8);
        uint32_t cb = (DIR == 0) ? 128u : 0u;
        uint32_t o = (uint32_t)e * ER + cb + q * 16;
        *(uint4*)(sm + o)         = hv;
        *(uint4*)(sm + EA_LO + o) = lv;
    }
    // feats: cols 128-131 = feat[row], 132-135 = feat[col]
    if (tid < 64) {
        int e = tid;
        int rowIdx = (DIR == 0) ? (p0 + (e >> 1)) : idx[e];
        int colIdx = (DIR == 0) ? idx[e] : (p0 + (e >> 1));
        uint2 rh = *(const uint2*)(fhi + (size_t)rowIdx * 4);
        uint2 ch = *(const uint2*)(fhi + (size_t)colIdx * 4);
        uint2 rl = *(const uint2*)(flo + (size_t)rowIdx * 4);
        uint2 cl = *(const uint2*)(flo + (size_t)colIdx * 4);
        uint32_t o = (uint32_t)e * ER + 256;
        *(uint4*)(sm + o)         = make_uint4(rh.x, rh.y, ch.x, ch.y);
        *(uint4*)(sm + EA_LO + o) = make_uint4(rl.x, rl.y, cl.x, cl.y);
    }
    __syncthreads();

    const int w = tid >> 5, lane = tid & 31;
    const int mbase = (w & 1) * 32;
    const int nb32  = (w >> 1) * 32;
    const int nb16  = (w >> 1) * 16;
    float acc[32];

    // ---- layer 1: K=136 (8 k16 + k8 tail), N=128 ----
    MBARRIER_WAIT_PARITY(mbw, 0);
    #pragma unroll
    for (int i = 0; i < 32; i++) acc[i] = 0.f;
    layer_mma_s<8, 2>(smb, smb + SM_W, ER, EA_LO, EW_LO128, lane, mbase, nb32, acc);
    layer1_tail(smb, smb + SM_W, lane, mbase, nb32, acc);
    __syncthreads();
    if (tid == 0) {
        MBARRIER_EXPECT_TX(mbw, 69632u);
        bulk_copy_g2s(smb + SM_W, wsrc + 69632, 69632u, mbw);
    }
    epi12(sm, bias_s, lane, mbase, nb32, acc);
    __syncthreads();

    // ---- layer 2: K=128, N=128 ----
    MBARRIER_WAIT_PARITY(mbw, 1);
    #pragma unroll
    for (int i = 0; i < 32; i++) acc[i] = 0.f;
    layer_mma_s<8, 2>(smb, smb + SM_W, ER, EA_LO, EW_LO128, lane, mbase, nb32, acc);
    __syncthreads();
    if (tid == 0) {
        MBARRIER_EXPECT_TX(mbw, 34816u);
        bulk_copy_g2s(smb + SM_W, wsrc + 139264, 34816u, mbw);
    }
    epi12(sm, bias_s + 128, lane, mbase, nb32, acc);
    __syncthreads();

    // ---- layer 3: K=128, N=64 ----
    MBARRIER_WAIT_PARITY(mbw, 0);
    #pragma unroll
    for (int i = 0; i < 16; i++) acc[i] = 0.f;
    layer_mma_s<8, 1>(smb, smb + SM_W, ER, EA_LO, EW_LO64, lane, mbase, nb16, acc);

    if (DIR == 0) {
        // atomic scatter: nm[col] += msg
        #pragma unroll
        for (int m = 0; m < 2; m++)
            #pragma unroll
            for (int h = 0; h < 2; h++) {
                const float* d = acc + (m * 2 + h) * 4;
                int c = nb16 + h * 8 + 2 * (lane & 3);
                int r = mbase + m * 16 + (lane >> 2);
                float b0 = bias_s[256 + c], b1v = bias_s[256 + c + 1];
                float* q0 = nm + (size_t)idx[r] * 64 + c;
                float* q1 = nm + (size_t)idx[r + 8] * 64 + c;
                atomicAdd(q0,     d[0] + b0);
                atomicAdd(q0 + 1, d[1] + b1v);
                atomicAdd(q1,     d[2] + b0);
                atomicAdd(q1 + 1, d[3] + b1v);
            }
    } else {
        // pair-sum scatter: nm[p0 + r] = msg[2r] + msg[2r+1], plain stores
        __syncthreads();                       // done reading A region
        float* st = (float*)sm;                // [64][68] f32 staging
        #pragma unroll
        for (int m = 0; m < 2; m++)
            #pragma unroll
            for (int h = 0; h < 2; h++) {
                const float* d = acc + (m * 2 + h) * 4;
                int c = nb16 + h * 8 + 2 * (lane & 3);
                int r = mbase + m * 16 + (lane >> 2);
                float b0 = bias_s[256 + c], b1v = bias_s[256 + c + 1];
                st[r * 68 + c]           = d[0] + b0;
                st[r * 68 + c + 1]       = d[1] + b1v;
                st[(r + 8) * 68 + c]     = d[2] + b0;
                st[(r + 8) * 68 + c + 1] = d[3] + b1v;
            }
        __syncthreads();
        for (int i = tid; i < 2048; i += 256) {
            int r = i >> 6, c = i & 63;
            nm[(size_t)(p0 + r) * 64 + c] = st[(2 * r) * 68 + c] + st[(2 * r + 1) * 68 + c];
        }
    }
}

// ---------------- HMMA GRU: [x|h](128x128) @ W'(256x128)^T ------------------
// writes h (f32) AND hi/lo bf16 planes for the next edge pass
#define GSM_W    69632
#define GSM_BIAS 208896
#define GSM_MBW  209920
#define GRU_SMEM_BYTES 209952
__global__ __launch_bounds__(512, 1) void gru_mma_kernel(
    float* __restrict__ h,
    __nv_bfloat16* __restrict__ h_hi, __nv_bfloat16* __restrict__ h_lo,
    float* __restrict__ x,
    const unsigned char* __restrict__ wsrc,
    const float* __restrict__ bih, const float* __restrict__ bhh,
    int nrows)
{
    extern __shared__ __align__(256) unsigned char sm[];
    const uint32_t smb = smem_u32(sm);
    const int tid = threadIdx.x;
    const int r0 = blockIdx.x * 128;

    float* bias_s = (float*)(sm + GSM_BIAS);
    float* gs     = (float*)(sm + GSM_W);
    const uint32_t mbw = smb + GSM_MBW;

    if (tid == 0) MBARRIER_INIT(mbw, 1u);
    __syncthreads();
    if (tid == 0) {
        MBARRIER_EXPECT_TX(mbw, 139264u);
        bulk_copy_g2s(smb + GSM_W, wsrc, 139264u, mbw);
    }
    for (int i = tid; i < 256; i += 512) {
        float v;
        if (i < 128)      v = bih[i] + bhh[i];
        else if (i < 192) v = bih[i];
        else              v = bhh[i - 64];
        bias_s[i] = v;
    }

    for (int i = tid; i < 128 * 32; i += 512) {
        int e = i >> 5, q = i & 31;
        int rr = r0 + e;
        int rc = rr < nrows ? rr : nrows - 1;
        float4 xv;
        if (q < 16) {
            xv = *(const float4*)(x + (size_t)rc * 64 + q * 4);
            if (rr < nrows) *(float4*)(x + (size_t)rc * 64 + q * 4) = make_float4(0.f, 0.f, 0.f, 0.f);
        } else {
            xv = *(const float4*)(h + (size_t)rc * 64 + (q - 16) * 4);
        }
        __nv_bfloat162 h01 = __floats2bfloat162_rn(xv.x, xv.y);
        __nv_bfloat162 h23 = __floats2bfloat162_rn(xv.z, xv.w);
        __nv_bfloat162 l01 = __floats2bfloat162_rn(xv.x - __low2float(h01), xv.y - __high2float(h01));
        __nv_bfloat162 l23 = __floats2bfloat162_rn(xv.z - __low2float(h23), xv.w - __high2float(h23));
        uint32_t off = (uint32_t)e * GR + (uint32_t)q * 8;
        *(uint2*)(sm + off)         = make_uint2(*(uint32_t*)&h01, *(uint32_t*)&h23);
        *(uint2*)(sm + GA_LO + off) = make_uint2(*(uint32_t*)&l01, *(uint32_t*)&l23);
    }
    __syncthreads();

    const int w = tid >> 5, lane = tid & 31;
    const int mbase = (w & 3) * 32;
    const int nbase = (w >> 2) * 64;
    float acc[64];
    #pragma unroll
    for (int i = 0; i < 64; i++) acc[i] = 0.f;

    MBARRIER_WAIT_PARITY(mbw, 0);
    layer_mma_s<8, 4>(smb, smb + GSM_W, GR, GA_LO, GW_LO, lane, mbase, nbase, acc);
    __syncthreads();

    #pragma unroll
    for (int m = 0; m < 2; m++)
        #pragma unroll
        for (int np = 0; np < 4; np++)
            #pragma unroll
            for (int hh = 0; hh < 2; hh++) {
                const float* d = acc + ((m * 4 + np) * 2 + hh) * 4;
                int c = nbase + np * 16 + hh * 8 + 2 * (lane & 3);
                int r = mbase + m * 16 + (lane >> 2);
                gs[r * 256 + c]           = d[0];
                gs[r * 256 + c + 1]       = d[1];
                gs[(r + 8) * 256 + c]     = d[2];
                gs[(r + 8) * 256 + c + 1] = d[3];
            }
    __syncthreads();

    for (int i = tid; i < 128 * 64; i += 512) {
        int e = i >> 6, d = i & 63;
        int r = r0 + e;
        if (r >= nrows) continue;
        const float* g = gs + e * 256;
        float pr = g[d]       + bias_s[d];
        float pz = g[64 + d]  + bias_s[64 + d];
        float in = g[128 + d] + bias_s[128 + d];
        float hn = g[192 + d] + bias_s[192 + d];
        float rr = 1.f / (1.f + expf(-pr));
        float zz = 1.f / (1.f + expf(-pz));
        float nn = tanhf(in + rr * hn);
        float hv = h[(size_t)r * 64 + d];
        float hnew = (1.f - zz) * nn + zz * hv;
        h[(size_t)r * 64 + d] = hnew;
        __nv_bfloat16 hb = __float2bfloat16(hnew);
        h_hi[(size_t)r * 64 + d] = hb;
        h_lo[(size_t)r * 64 + d] = __float2bfloat16(hnew - __bfloat162float(hb));
    }
}

// ---------------- readout ----------------
__global__ __launch_bounds__(256) void readout_kernel(
    const float* __restrict__ h,
    const float* __restrict__ W1, const float* __restrict__ b1,
    const float* __restrict__ W2, const float* __restrict__ b2,
    const float* __restrict__ W3, const float* __restrict__ b3,
    float* __restrict__ out, int nrows)
{
    __shared__ float hs[32 * 68];
    __shared__ float l1s[32 * 132];
    __shared__ float l2s[32 * 132];
    __shared__ float lg[64];

    const int tid = threadIdx.x;
    const int r0  = blockIdx.x * 32;

    for (int i = tid; i < 32 * 64; i += 256) {
        int e = i >> 6, k = i & 63;
        int r = r0 + e;
        hs[e * 68 + k] = (r < nrows) ? h[(size_t)r * 64 + k] : 0.f;
    }
    __syncthreads();

    const int warp = tid >> 5, lane = tid & 31;
    #pragma unroll
    for (int jc = 0; jc < 4; jc++) {
        const int j0 = warp * 16 + jc * 4;
        float a[4] = {0.f, 0.f, 0.f, 0.f};
        #pragma unroll
        for (int k = 0; k < 64; k += 4) {
            float4 xv = *(const float4*)(hs + lane * 68 + k);
            #pragma unroll
            for (int jj = 0; jj < 4; jj++) {
                float4 wv = *(const float4*)(W1 + (size_t)(j0 + jj) * 64 + k);
                a[jj] += wv.x * xv.x + wv.y * xv.y + wv.z * xv.z + wv.w * xv.w;
            }
        }
        #pragma unroll
        for (int jj = 0; jj < 4; jj++)
            l1s[lane * 132 + j0 + jj] = fmaxf(a[jj] + b1[j0 + jj], 0.f);
    }
    __syncthreads();
    #pragma unroll
    for (int jc = 0; jc < 4; jc++) {
        const int j0 = warp * 16 + jc * 4;
        float a[4] = {0.f, 0.f, 0.f, 0.f};
        #pragma unroll 2
        for (int k = 0; k < 128; k += 4) {
            float4 xv = *(const float4*)(l1s + lane * 132 + k);
            #pragma unroll
            for (int jj = 0; jj < 4; jj++) {
                float4 wv = *(const float4*)(W2 + (size_t)(j0 + jj) * 128 + k);
                a[jj] += wv.x * xv.x + wv.y * xv.y + wv.z * xv.z + wv.w * xv.w;
            }
        }
        #pragma unroll
        for (int jj = 0; jj < 4; jj++)
            l2s[lane * 132 + j0 + jj] = fmaxf(a[jj] + b2[j0 + jj], 0.f);
    }
    __syncthreads();
    if (tid < 64) {
        int e = tid >> 1, j = tid & 1;
        float a = 0.f;
        #pragma unroll 4
        for (int k = 0; k < 128; k += 4) {
            float4 xv = *(const float4*)(l2s + e * 132 + k);
            float4 wv = *(const float4*)(W3 + (size_t)j * 128 + k);
            a += wv.x * xv.x + wv.y * xv.y + wv.z * xv.z + wv.w * xv.w;
        }
        lg[e * 2 + j] = a + b3[j];
    }
    __syncthreads();
    if (tid < 64) {
        int e = tid >> 1, j = tid & 1;
        int r = r0 + e;
        if (r < nrows) {
            float self  = lg[e * 2 + j];
            float other = lg[e * 2 + (j ^ 1)];
            out[(size_t)r * 2 + j] = 1.f / (1.f + expf(other - self));
        }
    }
}

extern "C" void kernel_launch(void* const* d_in, const int* in_sizes, int n_in,
                              void* d_out, int out_size)
{
    const int*   f2v_col  = (const int*)d_in[1];
    const int*   v2f_row  = (const int*)d_in[2];
    const float* f2v_feat = (const float*)d_in[4];
    const float* v2f_feat = (const float*)d_in[5];
    const float* f2v_w1 = (const float*)d_in[6];   const float* f2v_b1 = (const float*)d_in[7];
    const float* f2v_w2 = (const float*)d_in[8];   const float* f2v_b2 = (const float*)d_in[9];
    const float* f2v_w3 = (const float*)d_in[10];  const float* f2v_b3 = (const float*)d_in[11];
    const float* v2f_w1 = (const float*)d_in[12];  const float* v2f_b1 = (const float*)d_in[13];
    const float* v2f_w2 = (const float*)d_in[14];  const float* v2f_b2 = (const float*)d_in[15];
    const float* v2f_w3 = (const float*)d_in[16];  const float* v2f_b3 = (const float*)d_in[17];
    const float* gf_wih = (const float*)d_in[18];  const float* gf_whh = (const float*)d_in[19];
    const float* gf_bih = (const float*)d_in[20];  const float* gf_bhh = (const float*)d_in[21];
    const float* gv_wih = (const float*)d_in[22];  const float* gv_whh = (const float*)d_in[23];
    const float* gv_bih = (const float*)d_in[24];  const float* gv_bhh = (const float*)d_in[25];
    const float* ro_w1  = (const float*)d_in[26];  const float* ro_b1  = (const float*)d_in[27];
    const float* ro_w2  = (const float*)d_in[28];  const float* ro_b2  = (const float*)d_in[29];
    const float* ro_w3  = (const float*)d_in[30];  const float* ro_b3  = (const float*)d_in[31];
    float* out = (float*)d_out;

    float *var_h, *fac_h, *nm_var, *nm_fac;
    __nv_bfloat16 *var_hhi, *var_hlo, *fac_hhi, *fac_hlo;
    __nv_bfloat16 *f2v_fhi, *f2v_flo, *v2f_fhi, *v2f_flo;
    unsigned char *wp_f2v, *wp_v2f, *wg_gf, *wg_gv;
    cudaGetSymbolAddress((void**)&var_h,   g_var_h);
    cudaGetSymbolAddress((void**)&fac_h,   g_fac_h);
    cudaGetSymbolAddress((void**)&nm_var,  g_nm_var);
    cudaGetSymbolAddress((void**)&nm_fac,  g_nm_fac);
    cudaGetSymbolAddress((void**)&var_hhi, g_var_hhi);
    cudaGetSymbolAddress((void**)&var_hlo, g_var_hlo);
    cudaGetSymbolAddress((void**)&fac_hhi, g_fac_hhi);
    cudaGetSymbolAddress((void**)&fac_hlo, g_fac_hlo);
    cudaGetSymbolAddress((void**)&f2v_fhi, g_f2v_fhi);
    cudaGetSymbolAddress((void**)&f2v_flo, g_f2v_flo);
    cudaGetSymbolAddress((void**)&v2f_fhi, g_v2f_fhi);
    cudaGetSymbolAddress((void**)&v2f_flo, g_v2f_flo);
    cudaGetSymbolAddress((void**)&wp_f2v,  g_wpack_f2v);
    cudaGetSymbolAddress((void**)&wp_v2f,  g_wpack_v2f);
    cudaGetSymbolAddress((void**)&wg_gf,   g_wgru_gf);
    cudaGetSymbolAddress((void**)&wg_gv,   g_wgru_gv);

    cudaFuncSetAttribute(edge_mma_kernel<0>, cudaFuncAttributeMaxDynamicSharedMemorySize, EDGE_SMEM_BYTES);
    cudaFuncSetAttribute(edge_mma_kernel<1>, cudaFuncAttributeMaxDynamicSharedMemorySize, EDGE_SMEM_BYTES);
    cudaFuncSetAttribute(gru_mma_kernel,     cudaFuncAttributeMaxDynamicSharedMemorySize, GRU_SMEM_BYTES);

    pack_weights_kernel<<<32, 256>>>(wp_f2v,           f2v_w1, 128, 136);
    pack_weights_kernel<<<32, 256>>>(wp_f2v + 69632,   f2v_w2, 128, 128);
    pack_weights_kernel<<<32, 256>>>(wp_f2v + 139264,  f2v_w3,  64, 128);
    pack_weights_kernel<<<32, 256>>>(wp_v2f,           v2f_w1, 128, 136);
    pack_weights_kernel<<<32, 256>>>(wp_v2f + 69632,   v2f_w2, 128, 128);
    pack_weights_kernel<<<32, 256>>>(wp_v2f + 139264,  v2f_w3,  64, 128);
    pack_gru_kernel<<<32, 256>>>(wg_gf, gf_wih, gf_whh);
    pack_gru_kernel<<<32, 256>>>(wg_gv, gv_wih, gv_whh);
    pack_split_kernel<<<64, 256>>>(f2v_fhi, f2v_flo, f2v_feat, NE * 4);
    pack_split_kernel<<<64, 256>>>(v2f_fhi, v2f_flo, v2f_feat, NE * 4);

    zero_kernel<<<256, 256>>>(var_h, NV * 64);
    zero_kernel<<<512, 256>>>(fac_h, NF * 64);
    zero_kernel<<<256, 256>>>(nm_var, NV * 64);
    zero_kernel<<<256, 256>>>((float*)var_hhi, NV * 32);
    zero_kernel<<<256, 256>>>((float*)var_hlo, NV * 32);
    zero_kernel<<<512, 256>>>((float*)fac_hhi, NF * 32);
    zero_kernel<<<512, 256>>>((float*)fac_hlo, NF * 32);

    for (int s = 0; s < 5; s++) {
        edge_mma_kernel<0><<<NE / 64, 256, EDGE_SMEM_BYTES>>>(
            fac_hhi, fac_hlo, var_hhi, var_hlo, f2v_col, f2v_fhi, f2v_flo,
            wp_f2v, f2v_b1, f2v_b2, f2v_b3, nm_var);
        gru_mma_kernel<<<(NV + 127) / 128, 512, GRU_SMEM_BYTES>>>(
            var_h, var_hhi, var_hlo, nm_var, wg_gf, gf_bih, gf_bhh, NV);

        edge_mma_kernel<1><<<NE / 64, 256, EDGE_SMEM_BYTES>>>(
            var_hhi, var_hlo, fac_hhi, fac_hlo, v2f_row, v2f_fhi, v2f_flo,
            wp_v2f, v2f_b1, v2f_b2, v2f_b3, nm_fac);
        gru_mma_kernel<<<NF / 128, 512, GRU_SMEM_BYTES>>>(
            fac_h, fac_hhi, fac_hlo, nm_fac, wg_gv, gv_bih, gv_bhh, NF);
    }

    readout_kernel<<<(NV + 31) / 32, 256>>>(
        var_h, ro_w1, ro_b1, ro_w2, ro_b2, ro_w3, ro_b3, out, NV);
}